// round 2
// baseline (speedup 1.0000x reference)
#include <cuda_runtime.h>
#include <cuda_bf16.h>
#include <cstdint>
#include <cstddef>

#define LOG2E 1.4426950408889634f
#define LN2   0.6931471805599453f

// ---- static scratch (no allocations allowed) ----
// cost in anti-diagonal layout, pre-scaled by log2e: g_cost[b][i+j][j], i,j in [0,256)
__device__ float g_cost[64 * 512 * 256];   // 33.5 MB
__device__ float g_xn[64 * 256];           // log2e * |x_i|^2
__device__ float g_yn[64 * 256];           // log2e * |y_j|^2

__device__ __forceinline__ float ex2f(float x) {
    float y; asm("ex2.approx.f32 %0, %1;" : "=f"(y) : "f"(x)); return y;
}
__device__ __forceinline__ float lg2f(float x) {
    float y; asm("lg2.approx.f32 %0, %1;" : "=f"(y) : "f"(x)); return y;
}

// ================= K0: row norms + zero output =================
__global__ void __launch_bounds__(512) norms_kernel(const float* __restrict__ x,
                                                    const float* __restrict__ y,
                                                    float* __restrict__ out) {
    int b = blockIdx.x, t = threadIdx.x;
    const float* src = (t < 256) ? (x + (size_t)(b * 256 + t) * 128)
                                 : (y + (size_t)(b * 256 + (t - 256)) * 128);
    const float4* v = (const float4*)src;
    float s = 0.f;
#pragma unroll
    for (int i = 0; i < 32; ++i) {
        float4 f = v[i];
        s = fmaf(f.x, f.x, s); s = fmaf(f.y, f.y, s);
        s = fmaf(f.z, f.z, s); s = fmaf(f.w, f.w, s);
    }
    s *= LOG2E;
    if (t < 256) g_xn[b * 256 + t] = s;
    else         g_yn[b * 256 + t - 256] = s;
    if (b == 0 && t == 0) out[0] = 0.f;
}

// ================= K1: cost GEMM, diagonal-layout epilogue =================
// grid = 64 batches * 4 tiles (2x2 of 128x128). 256 threads, 8x8 micro-tile each.
__global__ void __launch_bounds__(256) cost_gemm_kernel(const float* __restrict__ X,
                                                        const float* __restrict__ Y) {
    __shared__ float Xs[16][132];   // [k][m], padded
    __shared__ float Ys[16][132];   // [k][n], padded

    int bx = blockIdx.x;
    int b  = bx >> 2;
    int tm = (bx >> 1) & 1;
    int tn = bx & 1;
    int t  = threadIdx.x;
    int tx = t & 15, ty = t >> 4;

    const float* Xg = X + ((size_t)(b * 256 + tm * 128)) * 128;
    const float* Yg = Y + ((size_t)(b * 256 + tn * 128)) * 128;

    float acc[8][8];
#pragma unroll
    for (int r = 0; r < 8; ++r)
#pragma unroll
        for (int c = 0; c < 8; ++c) acc[r][c] = 0.f;

    int lr = t >> 1;          // 0..127 : row loaded by this thread
    int lk = (t & 1) * 8;     // 0 or 8 : k-offset within 16-chunk

    for (int kc = 0; kc < 128; kc += 16) {
        float4 xa = *(const float4*)(Xg + lr * 128 + kc + lk);
        float4 xb = *(const float4*)(Xg + lr * 128 + kc + lk + 4);
        float4 ya = *(const float4*)(Yg + lr * 128 + kc + lk);
        float4 yb = *(const float4*)(Yg + lr * 128 + kc + lk + 4);
        __syncthreads();   // previous chunk's reads complete
        Xs[lk + 0][lr] = xa.x; Xs[lk + 1][lr] = xa.y;
        Xs[lk + 2][lr] = xa.z; Xs[lk + 3][lr] = xa.w;
        Xs[lk + 4][lr] = xb.x; Xs[lk + 5][lr] = xb.y;
        Xs[lk + 6][lr] = xb.z; Xs[lk + 7][lr] = xb.w;
        Ys[lk + 0][lr] = ya.x; Ys[lk + 1][lr] = ya.y;
        Ys[lk + 2][lr] = ya.z; Ys[lk + 3][lr] = ya.w;
        Ys[lk + 4][lr] = yb.x; Ys[lk + 5][lr] = yb.y;
        Ys[lk + 6][lr] = yb.z; Ys[lk + 7][lr] = yb.w;
        __syncthreads();
#pragma unroll
        for (int kk = 0; kk < 16; ++kk) {
            float a[8], bb[8];
#pragma unroll
            for (int r = 0; r < 8; ++r) a[r]  = Xs[kk][ty * 8 + r];
#pragma unroll
            for (int c = 0; c < 8; ++c) bb[c] = Ys[kk][tx * 8 + c];
#pragma unroll
            for (int r = 0; r < 8; ++r)
#pragma unroll
                for (int c = 0; c < 8; ++c)
                    acc[r][c] = fmaf(a[r], bb[c], acc[r][c]);
        }
    }

    // epilogue: cost2 = xn + yn - 2*log2e*dot, scatter into diagonal layout
    float* cb = g_cost + (size_t)b * 512 * 256;
#pragma unroll
    for (int r = 0; r < 8; ++r) {
        int i = tm * 128 + ty * 8 + r;
        float xni = g_xn[b * 256 + i];
#pragma unroll
        for (int c = 0; c < 8; ++c) {
            int j = tn * 128 + tx * 8 + c;
            float v = xni + g_yn[b * 256 + j] - (2.0f * LOG2E) * acc[r][c];
            cb[(size_t)(i + j) * 256 + j] = v;
        }
    }
}

// ================= K2: soft-DTW wavefront DP =================
// One block per batch. Thread t owns DP column j = t+1 (1-indexed R of size 257x257).
// Anti-diagonal d = i + j runs 2..512. Log2 domain throughout.
__global__ void __launch_bounds__(256) dp_kernel(float* __restrict__ out) {
    __shared__ float buf[3][257];   // rotating diagonals, index = column 0..256

    int b = blockIdx.x, t = threadIdx.x;
    const float INF = __int_as_float(0x7f800000);

    // init: all three diagonals INF; R[0][0] = 0 lives on diag 0 (buf[0])
    buf[0][t + 1] = INF; buf[1][t + 1] = INF; buf[2][t + 1] = INF;
    if (t == 0) { buf[0][0] = 0.f; buf[1][0] = INF; buf[2][0] = INF; }
    __syncthreads();

    const float* cost = g_cost + (size_t)b * 512 * 256;

    // prefetch pipeline, depth 2: cp0 -> step d, cp1 -> step d+1
    float cp0 = cost[0 * 256 + t];   // for d=2 (s = d-2 = 0)
    float cp1 = cost[1 * 256 + t];   // for d=3

    int p2 = 0, p1 = 1, cu = 2;
    float r = INF;

    for (int d = 2; d <= 512; ++d) {
        float ccur = cp0;
        cp0 = cp1;
        cp1 = (d <= 510) ? cost[d * 256 + t] : 0.f;   // for step d+2

        int i = d - t - 1;                   // row for column j = t+1
        if (i >= 1 && i <= 256) {
            float a  = buf[p1][t + 1];       // R[i-1][j]
            float bb = buf[p1][t];           // R[i][j-1]
            float c  = buf[p2][t];           // R[i-1][j-1]
            float m  = fminf(a, fminf(bb, c));
            float s  = ex2f(m - a) + ex2f(m - bb) + ex2f(m - c);
            r = ccur + m - lg2f(s);
            buf[cu][t + 1] = r;
        }
        if (t == 0) buf[cu][0] = INF;        // R[d][0] = INF
        __syncthreads();
        int tmp = p2; p2 = p1; p1 = cu; cu = tmp;
    }

    // thread 255 last computed R[256][256] at d=512
    if (t == 255) atomicAdd(out, r * (LN2 / 64.0f));
}

extern "C" void kernel_launch(void* const* d_in, const int* in_sizes, int n_in,
                              void* d_out, int out_size) {
    const float* x = (const float*)d_in[0];
    const float* y = (const float*)d_in[1];
    float* out = (float*)d_out;
    norms_kernel<<<64, 512>>>(x, y, out);
    cost_gemm_kernel<<<256, 256>>>(x, y);
    dp_kernel<<<64, 256>>>(out);
}